// round 6
// baseline (speedup 1.0000x reference)
#include <cuda_runtime.h>
#include <cuda_fp16.h>
#include <cstdint>
#include <cstddef>

// Problem constants: B=4, I=64, O=64, K=3, H=W=512.
#define EPS_F 1e-8f

// ---------------------------------------------------------------------------
// Device scratch: modulated weights packed for LDS.64 B-fetch.
// Layout: g_wB[b][t(4)][ks(36)][col=o(64)][2 words], where for K16-step ks,
// word0 = half2 for kpair row (8*ks + t), word1 = kpair row (8*ks + t + 4).
// (kpair p holds input channels 2p, 2p+1 of tap ks/4.)
// ---------------------------------------------------------------------------
__device__ __align__(16) uint32_t g_wB[4 * 4 * 36 * 64 * 2];     // 294 KB

__device__ __forceinline__ uint32_t smem_u32(const void* p) {
    uint32_t a;
    asm("{ .reg .u64 t; cvta.to.shared.u64 t, %1; cvt.u32.u64 %0, t; }"
        : "=r"(a) : "l"(p));
    return a;
}

// ---------------------------------------------------------------------------
// Kernel 1: modulate + demodulate -> fp16 B-operand tiles (packed layout).
// ---------------------------------------------------------------------------
__global__ void modulate_kernel(const float* __restrict__ weight,   // (O=64, I=64, 3, 3)
                                const float* __restrict__ style) {  // (B=4, I=64)
    const int bo  = blockIdx.x;
    const int b   = bo >> 6;
    const int o   = bo & 63;
    const int tid = threadIdx.x;

    __shared__ float red[8];
    __shared__ float s_inv;

    float sum = 0.f;
    for (int idx = tid; idx < 576; idx += 256) {
        const int i = idx / 9;
        const float v = weight[o * 576 + idx] * style[b * 64 + i];
        sum += v * v;
    }
    #pragma unroll
    for (int off = 16; off; off >>= 1)
        sum += __shfl_down_sync(0xffffffffu, sum, off);
    if ((tid & 31) == 0) red[tid >> 5] = sum;
    __syncthreads();
    if (tid == 0) {
        float t = 0.f;
        #pragma unroll
        for (int k = 0; k < 8; k++) t += red[k];
        s_inv = rsqrtf(EPS_F + t);
    }
    __syncthreads();
    const float inv = s_inv;

    // 288 (ipair, tap) entries
    for (int idx = tid; idx < 288; idx += 256) {
        const int ip  = idx / 9;          // input-channel pair 0..31
        const int tap = idx - ip * 9;     // ky*3+kx
        const int i0  = 2 * ip;
        const float v0 = weight[o * 576 + i0 * 9 + tap]       * style[b * 64 + i0]     * inv;
        const float v1 = weight[o * 576 + (i0 + 1) * 9 + tap] * style[b * 64 + i0 + 1] * inv;
        __half2 h = __floats2half2_rn(v0, v1);
        const int kc = ip >> 3;           // K16 step within tap
        const int r  = ip & 7;            // kpair row within step
        const int t  = r & 3;
        const int hf = r >> 2;            // 0 -> b0 slot, 1 -> b1 slot
        const int ks = tap * 4 + kc;
        g_wB[(size_t)b * 18432 + (size_t)((t * 36 + ks) * 64 + o) * 2 + hf] =
            *reinterpret_cast<uint32_t*>(&h);
    }
}

// ---------------------------------------------------------------------------
// Kernel 2: fused fp32-NCHW load + fp16 mma.sync implicit-GEMM conv.
// CTA: 256 threads, output tile 8 rows x 16 cols (M=128 px), N=64, K=576.
// A: 10x18 halo tile, pixel-major fp16, pixel stride 72 halves (144 B).
//    Loaded straight from NCHW fp32 via aligned float4 chunks + cvt.
// B: packed [t(4)][ks(36)][col(64)][2] with +8 word pad per t block
//    (stride 4616 words) -> conflict-free LDS.64.
// Warp (wm = wid&3, wn = wid>>2): m32 (rows 2wm,2wm+1) x n32 (o base wn*32).
// ---------------------------------------------------------------------------
static constexpr int ASH_BYTES  = 180 * 144;              // 25920
static constexpr int B_TSTRIDE  = 36 * 64 * 2 + 8;        // 4616 words per t block
static constexpr int BSH_BYTES  = 4 * B_TSTRIDE * 4;      // 73856
static constexpr int CONV_SMEM  = ASH_BYTES + BSH_BYTES;  // 99776

__global__ __launch_bounds__(256, 2)
void conv_kernel(const float* __restrict__ input,   // (4, 64, 512, 512) fp32 NCHW
                 float* __restrict__ out) {         // (4, 64, 512, 512)
    extern __shared__ __align__(16) char dsm[];
    __half*    Ash = reinterpret_cast<__half*>(dsm);
    uint32_t*  Bsh = reinterpret_cast<uint32_t*>(dsm + ASH_BYTES);

    const int tid  = threadIdx.x;
    const int lane = tid & 31;
    const int wid  = tid >> 5;
    const int b    = blockIdx.z;
    const int y0   = blockIdx.y << 3;
    const int x0   = blockIdx.x << 4;

    // ---- fused transpose: fp32 NCHW -> fp16 pixel-major halo tile ----
    // Work item = (ch, halo row r, aligned float4 chunk c in [0,6)).
    // Chunk c covers gx in [x0-4+4c, x0+4c) -> tile px = 4c-3+j, j in [0,4).
    {
        const float* in_b = input + (size_t)b * (64 * 512 * 512);
        #pragma unroll 1
        for (int idx = tid; idx < 3840; idx += 256) {
            const int ch  = idx / 60;
            const int rem = idx - ch * 60;
            const int r   = rem / 6;
            const int c   = rem - r * 6;
            const int gy  = y0 - 1 + r;
            const int gx0 = x0 - 4 + 4 * c;
            const bool vload = ((unsigned)gy < 512u) && ((unsigned)gx0 < 512u);
            float4 v = make_float4(0.f, 0.f, 0.f, 0.f);
            if (vload)
                v = *reinterpret_cast<const float4*>(
                        in_b + ((size_t)ch << 18) + ((size_t)gy << 9) + gx0);
            const int pxb = 4 * c - 3;
            __half h[4];
            h[0] = __float2half_rn(v.x); h[1] = __float2half_rn(v.y);
            h[2] = __float2half_rn(v.z); h[3] = __float2half_rn(v.w);
            #pragma unroll
            for (int j = 0; j < 4; j++) {
                const int px = pxb + j;
                if ((unsigned)px < 18u)
                    Ash[(r * 18 + px) * 72 + ch] = h[j];
            }
        }
    }
    // ---- load B: 18432 words -> padded t-blocks ----
    {
        const uint4* src = reinterpret_cast<const uint4*>(g_wB + (size_t)b * 18432);
        for (int i4 = tid; i4 < 4608; i4 += 256) {
            const int t   = i4 / 1152;
            const int rem = i4 - t * 1152;
            *(reinterpret_cast<uint4*>(Bsh + t * B_TSTRIDE) + rem) = src[i4];
        }
    }
    __syncthreads();

    const int wm = wid & 3;    // m: tile rows 2wm, 2wm+1
    const int wn = wid >> 2;   // n: o range [wn*32, wn*32+32)

    float acc[2][4][4];
    #pragma unroll
    for (int mi = 0; mi < 2; mi++)
        #pragma unroll
        for (int ni = 0; ni < 4; ni++)
            #pragma unroll
            for (int j = 0; j < 4; j++) acc[mi][ni][j] = 0.f;

    // ldmatrix lane addresses: row = pixel x-offset (lane&15), col-half = lane>>4.
    const uint32_t ashu = smem_u32(Ash);
    uint32_t aAddr[2];
    #pragma unroll
    for (int mi = 0; mi < 2; mi++)
        aAddr[mi] = ashu + (uint32_t)(((2 * wm + mi) * 18 + (lane & 15)) * 144)
                         + (uint32_t)((lane >> 4) * 16);

    // B lane base (word index): t = lane&3 block, col = wn*32 + (lane>>2)
    const uint32_t* Blane = Bsh + (lane & 3) * B_TSTRIDE
                                + (wn * 32 + (lane >> 2)) * 2;

    #pragma unroll
    for (int tap = 0; tap < 9; tap++) {
        const uint32_t aoff = (uint32_t)(((tap / 3) * 18 + (tap % 3)) * 144);
        #pragma unroll
        for (int kc = 0; kc < 4; kc++) {
            uint32_t a[2][4];
            #pragma unroll
            for (int mi = 0; mi < 2; mi++)
                asm volatile(
                    "ldmatrix.sync.aligned.m8n8.x4.shared.b16 {%0,%1,%2,%3}, [%4];"
                    : "=r"(a[mi][0]), "=r"(a[mi][1]), "=r"(a[mi][2]), "=r"(a[mi][3])
                    : "r"(aAddr[mi] + aoff + (uint32_t)(kc * 32)));

            const int ks = tap * 4 + kc;                 // K16-step index
            const uint32_t* Bks = Blane + ks * 128;
            #pragma unroll
            for (int ni = 0; ni < 4; ni++) {
                const uint2 bv = *reinterpret_cast<const uint2*>(Bks + ni * 16);
                #pragma unroll
                for (int mi = 0; mi < 2; mi++)
                    asm volatile(
                        "mma.sync.aligned.m16n8k16.row.col.f32.f16.f16.f32 "
                        "{%0,%1,%2,%3}, {%4,%5,%6,%7}, {%8,%9}, {%0,%1,%2,%3};"
                        : "+f"(acc[mi][ni][0]), "+f"(acc[mi][ni][1]),
                          "+f"(acc[mi][ni][2]), "+f"(acc[mi][ni][3])
                        : "r"(a[mi][0]), "r"(a[mi][1]), "r"(a[mi][2]), "r"(a[mi][3]),
                          "r"(bv.x), "r"(bv.y));
            }
        }
    }

    // ---- epilogue: c0,c1 -> (x, o), (x, o+1); c2,c3 -> (x+8, o), (x+8, o+1) ----
    const int xg = x0 + (lane >> 2);
    const int og = wn * 32 + 2 * (lane & 3);
    #pragma unroll
    for (int mi = 0; mi < 2; mi++) {
        const int y = y0 + 2 * wm + mi;
        #pragma unroll
        for (int ni = 0; ni < 4; ni++) {
            float* p = out + ((size_t)(b * 64 + og + ni * 8) << 18)
                           + ((size_t)y << 9) + xg;
            p[0]               = acc[mi][ni][0];
            p[(size_t)1 << 18] = acc[mi][ni][1];
            p[8]               = acc[mi][ni][2];
            p[((size_t)1 << 18) + 8] = acc[mi][ni][3];
        }
    }
}

// ---------------------------------------------------------------------------
// Harness entry point.
//   d_in[0] = input  (4, 64, 512, 512) float
//   d_in[1] = style  (4, 64)           float
//   d_in[2] = weight (64, 64, 3, 3)    float
//   d_out   = (4, 64, 512, 512) float
// ---------------------------------------------------------------------------
extern "C" void kernel_launch(void* const* d_in, const int* in_sizes, int n_in,
                              void* d_out, int out_size) {
    const float* input  = (const float*)d_in[0];
    const float* style  = (const float*)d_in[1];
    const float* weight = (const float*)d_in[2];
    float* out = (float*)d_out;

    cudaFuncSetAttribute(conv_kernel, cudaFuncAttributeMaxDynamicSharedMemorySize,
                         CONV_SMEM);

    modulate_kernel<<<256, 256>>>(weight, style);
    conv_kernel<<<dim3(32, 64, 4), 256, CONV_SMEM>>>(input, out);
}

// round 7
// speedup vs baseline: 1.4469x; 1.4469x over previous
#include <cuda_runtime.h>
#include <cuda_fp16.h>
#include <cstdint>
#include <cstddef>

// Problem constants: B=4, I=64, O=64, K=3, H=W=512.
#define EPS_F 1e-8f

// ---------------------------------------------------------------------------
// Device scratch.
// ---------------------------------------------------------------------------
// Input transposed to HWC fp16: g_hwc[b][y][x][i], 128 B per pixel.
__device__ __align__(16) __half g_hwc[(size_t)4 * 512 * 512 * 64];   // 128 MB
// Modulated weights packed for LDS.64 B-fetch:
// g_wB[b][t(4)][ks(36)][col=o(64)][2 words]; for K16-step ks, word0 = half2 of
// kpair row (8*ks + t), word1 = kpair row (8*ks + t + 4).
__device__ __align__(16) uint32_t g_wB[4 * 4 * 36 * 64 * 2];         // 294 KB

__device__ __forceinline__ uint32_t smem_u32(const void* p) {
    uint32_t a;
    asm("{ .reg .u64 t; cvta.to.shared.u64 t, %1; cvt.u32.u64 %0, t; }"
        : "=r"(a) : "l"(p));
    return a;
}

// ---------------------------------------------------------------------------
// Kernel 1: modulate + demodulate -> packed fp16 B tiles.
// ---------------------------------------------------------------------------
__global__ void modulate_kernel(const float* __restrict__ weight,   // (O=64, I=64, 3, 3)
                                const float* __restrict__ style) {  // (B=4, I=64)
    const int bo  = blockIdx.x;
    const int b   = bo >> 6;
    const int o   = bo & 63;
    const int tid = threadIdx.x;

    __shared__ float red[8];
    __shared__ float s_inv;

    float sum = 0.f;
    for (int idx = tid; idx < 576; idx += 256) {
        const int i = idx / 9;
        const float v = weight[o * 576 + idx] * style[b * 64 + i];
        sum += v * v;
    }
    #pragma unroll
    for (int off = 16; off; off >>= 1)
        sum += __shfl_down_sync(0xffffffffu, sum, off);
    if ((tid & 31) == 0) red[tid >> 5] = sum;
    __syncthreads();
    if (tid == 0) {
        float t = 0.f;
        #pragma unroll
        for (int k = 0; k < 8; k++) t += red[k];
        s_inv = rsqrtf(EPS_F + t);
    }
    __syncthreads();
    const float inv = s_inv;

    for (int idx = tid; idx < 288; idx += 256) {
        const int ip  = idx / 9;          // input-channel pair 0..31
        const int tap = idx - ip * 9;     // ky*3+kx
        const int i0  = 2 * ip;
        const float v0 = weight[o * 576 + i0 * 9 + tap]       * style[b * 64 + i0]     * inv;
        const float v1 = weight[o * 576 + (i0 + 1) * 9 + tap] * style[b * 64 + i0 + 1] * inv;
        __half2 h = __floats2half2_rn(v0, v1);
        const int kc = ip >> 3;           // K16 step within tap
        const int r  = ip & 7;            // kpair row within step
        const int t  = r & 3;
        const int hf = r >> 2;            // 0 -> word0, 1 -> word1
        const int ks = tap * 4 + kc;
        g_wB[(size_t)b * 18432 + (size_t)((t * 36 + ks) * 64 + o) * 2 + hf] =
            *reinterpret_cast<uint32_t*>(&h);
    }
}

// ---------------------------------------------------------------------------
// Kernel 2: NCHW fp32 -> HWC fp16 transpose (ALU-bound on the cvt; loads
// vectorized to float4 for MLP).
// ---------------------------------------------------------------------------
__global__ __launch_bounds__(256)
void transpose_kernel(const float* __restrict__ input) {  // (4, 64, 512, 512)
    __shared__ float s[64][129];
    const int tid = threadIdx.x;
    const int b   = blockIdx.z;
    const int y   = blockIdx.y;
    const int x0  = blockIdx.x << 7;

    #pragma unroll
    for (int it = 0; it < 8; it++) {
        const int idx = it * 256 + tid;          // 2048 float4 slots
        const int i   = idx >> 5;                // channel
        const int xq  = idx & 31;                // float4 index within 128 px
        const float4 v = *reinterpret_cast<const float4*>(
            input + ((size_t)(b * 64 + i) * 512 + y) * 512 + x0 + xq * 4);
        s[i][xq * 4 + 0] = v.x;
        s[i][xq * 4 + 1] = v.y;
        s[i][xq * 4 + 2] = v.z;
        s[i][xq * 4 + 3] = v.w;
    }
    __syncthreads();

    const int x = tid >> 1;
    const int h = tid & 1;          // channel half: [h*32, h*32+32)
    uint32_t pk[16];
    #pragma unroll
    for (int j = 0; j < 16; j++) {
        __half2 hh = __floats2half2_rn(s[h * 32 + 2 * j][x], s[h * 32 + 2 * j + 1][x]);
        pk[j] = *reinterpret_cast<uint32_t*>(&hh);
    }
    __half* dst = g_hwc + ((size_t)(b * 512 + y) * 512 + x0 + x) * 64 + h * 32;
    uint4* d4 = reinterpret_cast<uint4*>(dst);
    #pragma unroll
    for (int j = 0; j < 4; j++)
        d4[j] = make_uint4(pk[4*j], pk[4*j+1], pk[4*j+2], pk[4*j+3]);
}

// ---------------------------------------------------------------------------
// Kernel 3: fp16 mma.sync implicit-GEMM conv.
// CTA: 256 threads, output tile 8 rows x 16 cols (M=128 px), N=64, K=576.
// A: 10x18 halo tile (HWC fp16 from g_hwc), pixel stride 72 halves (144 B).
// B: packed [t(4)][ks(36)][col(64)][2], t-block stride 4616 words
//    -> conflict-free LDS.64 (half-warp phases verified).
// Warp (wm = wid&3, wn = wid>>2): m32 (rows 2wm,2wm+1) x n32 (o base wn*32).
// Mainloop: 36 K16-steps, A-fragments double-buffered (ldmatrix 1 step ahead).
// ---------------------------------------------------------------------------
static constexpr int ASH_BYTES  = 180 * 144;              // 25920
static constexpr int B_TSTRIDE  = 36 * 64 * 2 + 8;        // 4616 words per t block
static constexpr int BSH_BYTES  = 4 * B_TSTRIDE * 4;      // 73856
static constexpr int CONV_SMEM  = ASH_BYTES + BSH_BYTES;  // 99776

__global__ __launch_bounds__(256, 2)
void conv_kernel(float* __restrict__ out) {               // (4, 64, 512, 512)
    extern __shared__ __align__(16) char dsm[];
    __half*    Ash = reinterpret_cast<__half*>(dsm);
    uint32_t*  Bsh = reinterpret_cast<uint32_t*>(dsm + ASH_BYTES);

    const int tid  = threadIdx.x;
    const int lane = tid & 31;
    const int wid  = tid >> 5;
    const int b    = blockIdx.z;
    const int y0   = blockIdx.y << 3;
    const int x0   = blockIdx.x << 4;

    // ---- load 10x18 px halo (HWC fp16), zero-padded at borders ----
    {
        const __half* src_b = g_hwc + (size_t)b * (512 * 512 * 64);
        #pragma unroll
        for (int it = 0; it < 6; it++) {                 // 1440 items
            const int idx = it * 256 + tid;
            if (idx < 1440) {
                const int p  = idx >> 3;
                const int ck = idx & 7;
                const int r  = p / 18;
                const int c  = p - r * 18;
                const int gy = y0 - 1 + r;
                const int gx = x0 - 1 + c;
                uint4 v = make_uint4(0u, 0u, 0u, 0u);
                if ((unsigned)gy < 512u && (unsigned)gx < 512u)
                    v = *reinterpret_cast<const uint4*>(
                            src_b + ((size_t)gy * 512 + gx) * 64 + ck * 8);
                *reinterpret_cast<uint4*>(Ash + p * 72 + ck * 8) = v;
            }
        }
    }
    // ---- load B: 18432 words -> padded t-blocks ----
    {
        const uint4* src = reinterpret_cast<const uint4*>(g_wB + (size_t)b * 18432);
        #pragma unroll
        for (int it = 0; it < 18; it++) {                // 4608 uint4
            const int i4  = it * 256 + tid;
            const int t   = i4 / 1152;
            const int rem = i4 - t * 1152;
            *(reinterpret_cast<uint4*>(Bsh + t * B_TSTRIDE) + rem) = src[i4];
        }
    }
    __syncthreads();

    const int wm = wid & 3;    // m: tile rows 2wm, 2wm+1
    const int wn = wid >> 2;   // n: o range [wn*32, wn*32+32)

    float acc[2][4][4];
    #pragma unroll
    for (int mi = 0; mi < 2; mi++)
        #pragma unroll
        for (int ni = 0; ni < 4; ni++)
            #pragma unroll
            for (int j = 0; j < 4; j++) acc[mi][ni][j] = 0.f;

    // ldmatrix lane addresses: row = pixel x-offset (lane&15), col-half = lane>>4.
    const uint32_t ashu = smem_u32(Ash);
    uint32_t aBase[2];
    #pragma unroll
    for (int mi = 0; mi < 2; mi++)
        aBase[mi] = ashu + (uint32_t)(((2 * wm + mi) * 18 + (lane & 15)) * 144)
                         + (uint32_t)((lane >> 4) * 16);

    // B lane base (word index): t = lane&3 block, col = wn*32 + (lane>>2)
    const uint32_t* Blane = Bsh + (lane & 3) * B_TSTRIDE
                                + (wn * 32 + (lane >> 2)) * 2;

    #define A_ADDR(mi, ks) (aBase[mi] \
        + (uint32_t)(((((ks) >> 2) / 3) * 18 + (((ks) >> 2) % 3)) * 144) \
        + (uint32_t)(((ks) & 3) * 32))
    #define LDSM4(dst, addr) \
        asm volatile("ldmatrix.sync.aligned.m8n8.x4.shared.b16 {%0,%1,%2,%3}, [%4];" \
            : "=r"((dst)[0]), "=r"((dst)[1]), "=r"((dst)[2]), "=r"((dst)[3]) \
            : "r"(addr))

    uint32_t af[2][2][4];    // [parity][mi][frag]
    LDSM4(af[0][0], A_ADDR(0, 0));
    LDSM4(af[0][1], A_ADDR(1, 0));

    #pragma unroll
    for (int ks = 0; ks < 36; ks++) {
        const int cur = ks & 1;
        const int nxt = cur ^ 1;
        if (ks < 35) {                       // prefetch next step's A fragments
            LDSM4(af[nxt][0], A_ADDR(0, ks + 1));
            LDSM4(af[nxt][1], A_ADDR(1, ks + 1));
        }
        const uint32_t* Bks = Blane + ks * 128;
        uint2 bv[4];
        #pragma unroll
        for (int ni = 0; ni < 4; ni++)
            bv[ni] = *reinterpret_cast<const uint2*>(Bks + ni * 16);

        #pragma unroll
        for (int ni = 0; ni < 4; ni++)
            #pragma unroll
            for (int mi = 0; mi < 2; mi++)
                asm volatile(
                    "mma.sync.aligned.m16n8k16.row.col.f32.f16.f16.f32 "
                    "{%0,%1,%2,%3}, {%4,%5,%6,%7}, {%8,%9}, {%0,%1,%2,%3};"
                    : "+f"(acc[mi][ni][0]), "+f"(acc[mi][ni][1]),
                      "+f"(acc[mi][ni][2]), "+f"(acc[mi][ni][3])
                    : "r"(af[cur][mi][0]), "r"(af[cur][mi][1]),
                      "r"(af[cur][mi][2]), "r"(af[cur][mi][3]),
                      "r"(bv[ni].x), "r"(bv[ni].y));
    }
    #undef A_ADDR
    #undef LDSM4

    // ---- epilogue: c0,c1 -> (x, o), (x, o+1); c2,c3 -> (x+8, o), (x+8, o+1) ----
    const int xg = x0 + (lane >> 2);
    const int og = wn * 32 + 2 * (lane & 3);
    #pragma unroll
    for (int mi = 0; mi < 2; mi++) {
        const int y = y0 + 2 * wm + mi;
        #pragma unroll
        for (int ni = 0; ni < 4; ni++) {
            float* p = out + ((size_t)(b * 64 + og + ni * 8) << 18)
                           + ((size_t)y << 9) + xg;
            p[0]               = acc[mi][ni][0];
            p[(size_t)1 << 18] = acc[mi][ni][1];
            p[8]               = acc[mi][ni][2];
            p[((size_t)1 << 18) + 8] = acc[mi][ni][3];
        }
    }
}

// ---------------------------------------------------------------------------
// Harness entry point.
//   d_in[0] = input  (4, 64, 512, 512) float
//   d_in[1] = style  (4, 64)           float
//   d_in[2] = weight (64, 64, 3, 3)    float
//   d_out   = (4, 64, 512, 512) float
// ---------------------------------------------------------------------------
extern "C" void kernel_launch(void* const* d_in, const int* in_sizes, int n_in,
                              void* d_out, int out_size) {
    const float* input  = (const float*)d_in[0];
    const float* style  = (const float*)d_in[1];
    const float* weight = (const float*)d_in[2];
    float* out = (float*)d_out;

    cudaFuncSetAttribute(conv_kernel, cudaFuncAttributeMaxDynamicSharedMemorySize,
                         CONV_SMEM);

    modulate_kernel<<<256, 256>>>(weight, style);
    transpose_kernel<<<dim3(4, 512, 4), 256>>>(input);
    conv_kernel<<<dim3(32, 64, 4), 256, CONV_SMEM>>>(out);
}